// round 15
// baseline (speedup 1.0000x reference)
#include <cuda_runtime.h>
#include <cuda_fp16.h>
#include <math.h>

#define NN 50000
#define EE 1600000
#define TOT (EE + NN)
#define HC 128
#define NEG_SLOPE 0.2f
#define NSCAN 49         // ceil(50000/1024) scan blocks, 1024 elems each
#define NPAD 50176       // 49*1024
#define M_BLK 128
#define G_GEMM 391       // ceil(50000/128)

// ---------------- scratch ----------------
__device__ __half   g_xh[NN * HC];     // fp16 projected features (gather source)
__device__ float    g_as[NN * 2];
__device__ float    g_ad[NN * 2];
__device__ __align__(16) int g_counts[NPAD];   // zero-init; self-resetting
__device__ __align__(16) int g_offsets[NPAD];  // [NN] holds grand total
__device__ __align__(16) unsigned g_pk[EE];    // (rank<<16)|src per edge
__device__ int      g_ssrc[TOT];
__device__ int      g_bsum[NSCAN];             // zero-init; reset by last scan block
__device__ int      g_done;                    // zero-init; reset by last scan block
__device__ unsigned g_Wb[8192];                // W in fp16 HMMA B-fragment order

// ---------------- 0) W -> fragment-ordered fp16 ----------------
__global__ void k_wconv(const float* __restrict__ W) {
    int id = blockIdx.x * blockDim.x + threadIdx.x;
    if (id >= 4096) return;
    int c = id >> 5, rem = id & 31, q = rem >> 3, j = rem & 7;
    int k0 = 16 * j + 2 * q;
    float w0 = W[(k0    ) * 128 + c];
    float w1 = W[(k0 + 1) * 128 + c];
    float w2 = W[(k0 + 8) * 128 + c];
    float w3 = W[(k0 + 9) * 128 + c];
    half2 b0 = __floats2half2_rn(w0, w1);
    half2 b1 = __floats2half2_rn(w2, w3);
    uint2 v;
    v.x = *(unsigned*)&b0;
    v.y = *(unsigned*)&b1;
    ((uint2*)g_Wb)[(c * 4 + q) * 8 + j] = v;
}

#define MMA16816(d0,d1,d2,d3,a0,a1,a2,a3,b0,b1) \
    asm volatile("mma.sync.aligned.m16n8k16.row.col.f32.f16.f16.f32 " \
        "{%0,%1,%2,%3}, {%4,%5,%6,%7}, {%8,%9}, {%0,%1,%2,%3};" \
        : "+f"(d0), "+f"(d1), "+f"(d2), "+f"(d3) \
        : "r"(a0), "r"(a1), "r"(a2), "r"(a3), "r"(b0), "r"(b1))

// ---------------- 1) fused tensor-core GEMM(+attn) and rank-histogram ------
__global__ void k_gemm_hist(const float* __restrict__ A,
                            const float* __restrict__ att_src,
                            const float* __restrict__ att_dst,
                            const int* __restrict__ ei) {
    __shared__ __align__(16) __half Ash[M_BLK * 136];

    if (blockIdx.x >= G_GEMM) {
        int t = (blockIdx.x - G_GEMM) * blockDim.x + threadIdx.x;
        if (t < EE / 4) {
            int4 s = ((const int4*)ei)[t];
            int4 d = ((const int4*)(ei + EE))[t];
            uint4 p;
            p.x = ((unsigned)atomicAdd(&g_counts[d.x], 1) << 16) | (unsigned)s.x;
            p.y = ((unsigned)atomicAdd(&g_counts[d.y], 1) << 16) | (unsigned)s.y;
            p.z = ((unsigned)atomicAdd(&g_counts[d.z], 1) << 16) | (unsigned)s.z;
            p.w = ((unsigned)atomicAdd(&g_counts[d.w], 1) << 16) | (unsigned)s.w;
            ((uint4*)g_pk)[t] = p;
        }
        return;
    }

    int tid = threadIdx.x;
    int w = tid >> 5, l = tid & 31;
    int row0 = blockIdx.x * M_BLK;

    const float4* Ag = (const float4*)A;
    for (int i = tid; i < M_BLK * 32; i += 256) {
        int r = i >> 5, kq = i & 31;
        int row = row0 + r;
        float4 v = (row < NN) ? Ag[(size_t)row * 32 + kq] : make_float4(0.f, 0.f, 0.f, 0.f);
        half2 h0 = __floats2half2_rn(v.x, v.y);
        half2 h1 = __floats2half2_rn(v.z, v.w);
        uint2 pk;
        pk.x = *(unsigned*)&h0;
        pk.y = *(unsigned*)&h1;
        *(uint2*)&Ash[r * 136 + kq * 4] = pk;
    }
    __syncthreads();

    int g = l >> 2;
    int q = l & 3;
    int kk = q * 2;
    int r1 = w * 16 + g;
    int r2 = r1 + 8;
    int growA = row0 + r1, growB = row0 + r2;

    unsigned a[8][4];
    #pragma unroll
    for (int j = 0; j < 8; j++) {
        a[j][0] = *(unsigned*)&Ash[r1 * 136 + j * 16 + kk];
        a[j][1] = *(unsigned*)&Ash[r2 * 136 + j * 16 + kk];
        a[j][2] = *(unsigned*)&Ash[r1 * 136 + j * 16 + kk + 8];
        a[j][3] = *(unsigned*)&Ash[r2 * 136 + j * 16 + kk + 8];
    }

    float ps0A = 0.f, ps1A = 0.f, pd0A = 0.f, pd1A = 0.f;
    float ps0B = 0.f, ps1B = 0.f, pd0B = 0.f, pd1B = 0.f;

    #pragma unroll
    for (int t = 0; t < 16; t++) {
        int c = 8 * t + g;
        const uint4* wb = (const uint4*)g_Wb + (size_t)(c * 4 + q) * 4;
        uint4 B0 = wb[0], B1 = wb[1], B2 = wb[2], B3 = wb[3];
        float d0 = 0.f, d1 = 0.f, d2 = 0.f, d3 = 0.f;
        MMA16816(d0, d1, d2, d3, a[0][0], a[0][1], a[0][2], a[0][3], B0.x, B0.y);
        MMA16816(d0, d1, d2, d3, a[1][0], a[1][1], a[1][2], a[1][3], B0.z, B0.w);
        MMA16816(d0, d1, d2, d3, a[2][0], a[2][1], a[2][2], a[2][3], B1.x, B1.y);
        MMA16816(d0, d1, d2, d3, a[3][0], a[3][1], a[3][2], a[3][3], B1.z, B1.w);
        MMA16816(d0, d1, d2, d3, a[4][0], a[4][1], a[4][2], a[4][3], B2.x, B2.y);
        MMA16816(d0, d1, d2, d3, a[5][0], a[5][1], a[5][2], a[5][3], B2.z, B2.w);
        MMA16816(d0, d1, d2, d3, a[6][0], a[6][1], a[6][2], a[6][3], B3.x, B3.y);
        MMA16816(d0, d1, d2, d3, a[7][0], a[7][1], a[7][2], a[7][3], B3.z, B3.w);

        int c0 = 8 * t + kk;
        if (growA < NN) {
            half2 hh = __floats2half2_rn(d0, d1);
            *(half2*)&g_xh[(size_t)growA * 128 + c0] = hh;
        }
        if (growB < NN) {
            half2 hh = __floats2half2_rn(d2, d3);
            *(half2*)&g_xh[(size_t)growB * 128 + c0] = hh;
        }
        float2 s2 = *(const float2*)(att_src + c0);
        float2 t2 = *(const float2*)(att_dst + c0);
        float psA_ = d0 * s2.x + d1 * s2.y;
        float pdA_ = d0 * t2.x + d1 * t2.y;
        float psB_ = d2 * s2.x + d3 * s2.y;
        float pdB_ = d2 * t2.x + d3 * t2.y;
        if (t < 8) { ps0A += psA_; pd0A += pdA_; ps0B += psB_; pd0B += pdB_; }
        else       { ps1A += psA_; pd1A += pdA_; ps1B += psB_; pd1B += pdB_; }
    }

    #pragma unroll
    for (int d = 1; d <= 2; d <<= 1) {
        ps0A += __shfl_xor_sync(0xffffffffu, ps0A, d);
        ps1A += __shfl_xor_sync(0xffffffffu, ps1A, d);
        pd0A += __shfl_xor_sync(0xffffffffu, pd0A, d);
        pd1A += __shfl_xor_sync(0xffffffffu, pd1A, d);
        ps0B += __shfl_xor_sync(0xffffffffu, ps0B, d);
        ps1B += __shfl_xor_sync(0xffffffffu, ps1B, d);
        pd0B += __shfl_xor_sync(0xffffffffu, pd0B, d);
        pd1B += __shfl_xor_sync(0xffffffffu, pd1B, d);
    }
    if (q == 0) {
        if (growA < NN) {
            *(float2*)&g_as[2 * growA] = make_float2(ps0A, ps1A);
            *(float2*)&g_ad[2 * growA] = make_float2(pd0A, pd1A);
        }
        if (growB < NN) {
            *(float2*)&g_as[2 * growB] = make_float2(ps0B, ps1B);
            *(float2*)&g_ad[2 * growB] = make_float2(pd0B, pd1B);
        }
    }
}

// ---------------- 2) single-pass decoupled-lookback scan -------------------
__global__ void k_scan() {
    __shared__ int warp_sums[8];
    __shared__ int warp_excl[8];
    __shared__ int s_prev;

    int b = blockIdx.x;
    int tid = threadIdx.x, lane = tid & 31, wid = tid >> 5;
    int base = b * 1024 + tid * 4;

    int4 c4 = *(int4*)&g_counts[base];
    int v0 = (base + 0 < NN) ? c4.x + 1 : 0;   // +1 self loop
    int v1 = (base + 1 < NN) ? c4.y + 1 : 0;
    int v2 = (base + 2 < NN) ? c4.z + 1 : 0;
    int v3 = (base + 3 < NN) ? c4.w + 1 : 0;
    int s = v0 + v1 + v2 + v3;

    int x = s;
    #pragma unroll
    for (int d = 1; d < 32; d <<= 1) {
        int t2 = __shfl_up_sync(0xffffffffu, x, d);
        if (lane >= d) x += t2;
    }
    if (lane == 31) warp_sums[wid] = x;
    __syncthreads();
    if (tid == 0) {
        int run = 0;
        #pragma unroll
        for (int i = 0; i < 8; i++) {
            int t2 = warp_sums[i];
            warp_excl[i] = run;
            run += t2;
        }
        atomicExch(&g_bsum[b], run);
    }
    __syncthreads();

    if (wid == 0) {
        int acc = 0;
        for (int p = lane; p < b; p += 32) {
            int v;
            do { v = ((volatile int*)g_bsum)[p]; } while (v == 0);
            acc += v;
        }
        #pragma unroll
        for (int d = 16; d >= 1; d >>= 1)
            acc += __shfl_xor_sync(0xffffffffu, acc, d);
        if (lane == 0) s_prev = acc;
    }
    __syncthreads();

    int excl = s_prev + warp_excl[wid] + (x - s);
    int4 ov = make_int4(excl, excl + v0, excl + v0 + v1, excl + v0 + v1 + v2);
    *(int4*)&g_offsets[base] = ov;
    *(int4*)&g_counts[base]  = make_int4(0, 0, 0, 0);

    __threadfence();
    __syncthreads();
    if (tid == 0) {
        int r = atomicAdd(&g_done, 1);
        if (r == NSCAN - 1) {
            for (int i = 0; i < NSCAN; i++) g_bsum[i] = 0;
            g_done = 0;
        }
    }
}

// ---------------- 3) scatter edges into CSR (atomic-free, packed) ----------
__global__ void k_scatter(const int* __restrict__ ei) {
    int t = blockIdx.x * blockDim.x + threadIdx.x;
    const int EQ = EE / 4;
    if (t < EQ) {
        int4 d = ((const int4*)(ei + EE))[t];
        uint4 p = ((const uint4*)g_pk)[t];
        g_ssrc[__ldg(&g_offsets[d.x]) + 1 + (int)(p.x >> 16)] = (int)(p.x & 0xFFFFu);
        g_ssrc[__ldg(&g_offsets[d.y]) + 1 + (int)(p.y >> 16)] = (int)(p.y & 0xFFFFu);
        g_ssrc[__ldg(&g_offsets[d.z]) + 1 + (int)(p.z >> 16)] = (int)(p.z & 0xFFFFu);
        g_ssrc[__ldg(&g_offsets[d.w]) + 1 + (int)(p.w >> 16)] = (int)(p.w & 0xFFFFu);
    } else if (t - EQ < NN) {
        int n = t - EQ;
        g_ssrc[__ldg(&g_offsets[n])] = n;
    }
}

// ---------------- 4) edge softmax + aggregate (smem-staged inner loop) -----
__device__ __forceinline__ float leaky(float x) {
    return x > 0.f ? x : NEG_SLOPE * x;
}

__global__ void __launch_bounds__(256, 8)
k_aggregate(const float* __restrict__ bias, float* __restrict__ out) {
    __shared__ float s_p[8][2][36];
    __shared__ int   s_off[8][32];

    int w = (blockIdx.x * blockDim.x + threadIdx.x) >> 5;
    if (w >= NN) return;
    int lane = threadIdx.x & 31;
    int h = lane >> 4;
    int ws = (threadIdx.x >> 5) & 7;
    int beg = g_offsets[w], end = g_offsets[w + 1];

    float ad0 = g_ad[2 * w + 0];
    float ad1 = g_ad[2 * w + 1];
    const char* xbase = (const char*)g_xh + lane * 8;

    float den0 = 0.f, den1 = 0.f;
    float4 acc = make_float4(0.f, 0.f, 0.f, 0.f);

    for (int base = beg; base < end; base += 32) {
        int nb = min(32, end - base);
        if (lane < nb) {
            int idx = g_ssrc[base + lane];
            float2 as2 = *(const float2*)&g_as[2 * idx];
            float p0 = __expf(leaky(as2.x + ad0));
            float p1 = __expf(leaky(as2.y + ad1));
            den0 += p0;
            den1 += p1;
            s_p[ws][0][lane] = p0;
            s_p[ws][1][lane] = p1;
            s_off[ws][lane] = idx << 8;
        }
        __syncwarp();
        if (nb == 32) {
            #pragma unroll 8
            for (int jj = 0; jj < 32; jj++) {
                int off = s_off[ws][jj];
                float ph = s_p[ws][h][jj];
                uint2 hv = *(const uint2*)(xbase + off);
                float2 f01 = __half22float2(*(half2*)&hv.x);
                float2 f23 = __half22float2(*(half2*)&hv.y);
                acc.x += ph * f01.x;
                acc.y += ph * f01.y;
                acc.z += ph * f23.x;
                acc.w += ph * f23.y;
            }
        } else {
            for (int jj = 0; jj < nb; jj++) {
                int off = s_off[ws][jj];
                float ph = s_p[ws][h][jj];
                uint2 hv = *(const uint2*)(xbase + off);
                float2 f01 = __half22float2(*(half2*)&hv.x);
                float2 f23 = __half22float2(*(half2*)&hv.y);
                acc.x += ph * f01.x;
                acc.y += ph * f01.y;
                acc.z += ph * f23.x;
                acc.w += ph * f23.y;
            }
        }
        __syncwarp();
    }

    #pragma unroll
    for (int d = 16; d >= 1; d >>= 1) {
        den0 += __shfl_xor_sync(0xffffffffu, den0, d);
        den1 += __shfl_xor_sync(0xffffffffu, den1, d);
    }
    float inv = 1.0f / (h ? den1 : den0);

    float4 b = ((const float4*)bias)[lane];
    acc.x = acc.x * inv + b.x;
    acc.y = acc.y * inv + b.y;
    acc.z = acc.z * inv + b.z;
    acc.w = acc.w * inv + b.w;
    acc.x = acc.x > 0.f ? acc.x : expm1f(acc.x);
    acc.y = acc.y > 0.f ? acc.y : expm1f(acc.y);
    acc.z = acc.z > 0.f ? acc.z : expm1f(acc.z);
    acc.w = acc.w > 0.f ? acc.w : expm1f(acc.w);
    ((float4*)out)[(size_t)w * 32 + lane] = acc;
}

// ---------------- launch ----------------
extern "C" void kernel_launch(void* const* d_in, const int* in_sizes, int n_in,
                              void* d_out, int out_size) {
    const float* h_node  = (const float*)d_in[0];
    const int*   ei      = (const int*)d_in[1];
    const float* W       = (const float*)d_in[2];
    const float* att_src = (const float*)d_in[3];
    const float* att_dst = (const float*)d_in[4];
    const float* bias    = (const float*)d_in[5];
    float* out = (float*)d_out;

    k_wconv<<<16, 256>>>(W);
    int hist_blocks = (EE / 4 + 255) / 256;
    k_gemm_hist<<<G_GEMM + hist_blocks, 256>>>(h_node, att_src, att_dst, ei);
    k_scan<<<NSCAN, 256>>>();
    k_scatter<<<(EE / 4 + NN + 255) / 256, 256>>>(ei);
    k_aggregate<<<(NN * 32 + 255) / 256, 256>>>(bias, out);
}

// round 16
// speedup vs baseline: 1.0790x; 1.0790x over previous
#include <cuda_runtime.h>
#include <cuda_fp16.h>
#include <math.h>

#define NN 50000
#define EE 1600000
#define TOT (EE + NN)
#define HC 128
#define NEG_SLOPE 0.2f
#define NSCAN 49         // ceil(50000/1024) scan blocks, 1024 elems each
#define NPAD 50176       // 49*1024
#define M_BLK 128
#define G_GEMM 391       // ceil(50000/128)

// ---------------- scratch ----------------
__device__ __half   g_xh[NN * HC];     // fp16 projected features (gather source)
__device__ float    g_as[NN * 2];
__device__ float    g_ad[NN * 2];
__device__ __align__(16) int g_counts[NPAD];   // zero-init; self-resetting
__device__ __align__(16) int g_offsets[NPAD];  // [NN] holds grand total
__device__ __align__(16) int g_rank[EE];       // per-edge rank within its dst
__device__ int      g_ssrc[TOT];
__device__ int      g_bsum[NSCAN];             // zero-init; reset by last scan block
__device__ int      g_done;                    // zero-init; reset by last scan block
__device__ unsigned g_Wb[8192];                // W in fp16 HMMA B-fragment order

// ---------------- 0) W -> fragment-ordered fp16 ----------------
__global__ void k_wconv(const float* __restrict__ W) {
    int id = blockIdx.x * blockDim.x + threadIdx.x;
    if (id >= 4096) return;
    int c = id >> 5, rem = id & 31, q = rem >> 3, j = rem & 7;
    int k0 = 16 * j + 2 * q;
    float w0 = W[(k0    ) * 128 + c];
    float w1 = W[(k0 + 1) * 128 + c];
    float w2 = W[(k0 + 8) * 128 + c];
    float w3 = W[(k0 + 9) * 128 + c];
    half2 b0 = __floats2half2_rn(w0, w1);
    half2 b1 = __floats2half2_rn(w2, w3);
    uint2 v;
    v.x = *(unsigned*)&b0;
    v.y = *(unsigned*)&b1;
    ((uint2*)g_Wb)[(c * 4 + q) * 8 + j] = v;
}

#define MMA16816(d0,d1,d2,d3,a0,a1,a2,a3,b0,b1) \
    asm volatile("mma.sync.aligned.m16n8k16.row.col.f32.f16.f16.f32 " \
        "{%0,%1,%2,%3}, {%4,%5,%6,%7}, {%8,%9}, {%0,%1,%2,%3};" \
        : "+f"(d0), "+f"(d1), "+f"(d2), "+f"(d3) \
        : "r"(a0), "r"(a1), "r"(a2), "r"(a3), "r"(b0), "r"(b1))

// ---------------- 1) fused tensor-core GEMM(+attn) and rank-histogram ------
__global__ void k_gemm_hist(const float* __restrict__ A,
                            const float* __restrict__ att_src,
                            const float* __restrict__ att_dst,
                            const int* __restrict__ ei) {
    __shared__ __align__(16) __half Ash[M_BLK * 136];

    if (blockIdx.x >= G_GEMM) {
        int t = (blockIdx.x - G_GEMM) * blockDim.x + threadIdx.x;
        if (t < EE / 4) {
            int4 d = ((const int4*)(ei + EE))[t];
            int4 r;
            r.x = atomicAdd(&g_counts[d.x], 1);
            r.y = atomicAdd(&g_counts[d.y], 1);
            r.z = atomicAdd(&g_counts[d.z], 1);
            r.w = atomicAdd(&g_counts[d.w], 1);
            ((int4*)g_rank)[t] = r;
        }
        return;
    }

    int tid = threadIdx.x;
    int w = tid >> 5, l = tid & 31;
    int row0 = blockIdx.x * M_BLK;

    const float4* Ag = (const float4*)A;
    for (int i = tid; i < M_BLK * 32; i += 256) {
        int r = i >> 5, kq = i & 31;
        int row = row0 + r;
        float4 v = (row < NN) ? Ag[(size_t)row * 32 + kq] : make_float4(0.f, 0.f, 0.f, 0.f);
        half2 h0 = __floats2half2_rn(v.x, v.y);
        half2 h1 = __floats2half2_rn(v.z, v.w);
        uint2 pk;
        pk.x = *(unsigned*)&h0;
        pk.y = *(unsigned*)&h1;
        *(uint2*)&Ash[r * 136 + kq * 4] = pk;
    }
    __syncthreads();

    int g = l >> 2;
    int q = l & 3;
    int kk = q * 2;
    int r1 = w * 16 + g;
    int r2 = r1 + 8;
    int growA = row0 + r1, growB = row0 + r2;

    unsigned a[8][4];
    #pragma unroll
    for (int j = 0; j < 8; j++) {
        a[j][0] = *(unsigned*)&Ash[r1 * 136 + j * 16 + kk];
        a[j][1] = *(unsigned*)&Ash[r2 * 136 + j * 16 + kk];
        a[j][2] = *(unsigned*)&Ash[r1 * 136 + j * 16 + kk + 8];
        a[j][3] = *(unsigned*)&Ash[r2 * 136 + j * 16 + kk + 8];
    }

    float ps0A = 0.f, ps1A = 0.f, pd0A = 0.f, pd1A = 0.f;
    float ps0B = 0.f, ps1B = 0.f, pd0B = 0.f, pd1B = 0.f;

    #pragma unroll
    for (int t = 0; t < 16; t++) {
        int c = 8 * t + g;
        const uint4* wb = (const uint4*)g_Wb + (size_t)(c * 4 + q) * 4;
        uint4 B0 = wb[0], B1 = wb[1], B2 = wb[2], B3 = wb[3];
        float d0 = 0.f, d1 = 0.f, d2 = 0.f, d3 = 0.f;
        MMA16816(d0, d1, d2, d3, a[0][0], a[0][1], a[0][2], a[0][3], B0.x, B0.y);
        MMA16816(d0, d1, d2, d3, a[1][0], a[1][1], a[1][2], a[1][3], B0.z, B0.w);
        MMA16816(d0, d1, d2, d3, a[2][0], a[2][1], a[2][2], a[2][3], B1.x, B1.y);
        MMA16816(d0, d1, d2, d3, a[3][0], a[3][1], a[3][2], a[3][3], B1.z, B1.w);
        MMA16816(d0, d1, d2, d3, a[4][0], a[4][1], a[4][2], a[4][3], B2.x, B2.y);
        MMA16816(d0, d1, d2, d3, a[5][0], a[5][1], a[5][2], a[5][3], B2.z, B2.w);
        MMA16816(d0, d1, d2, d3, a[6][0], a[6][1], a[6][2], a[6][3], B3.x, B3.y);
        MMA16816(d0, d1, d2, d3, a[7][0], a[7][1], a[7][2], a[7][3], B3.z, B3.w);

        int c0 = 8 * t + kk;
        if (growA < NN) {
            half2 hh = __floats2half2_rn(d0, d1);
            *(half2*)&g_xh[(size_t)growA * 128 + c0] = hh;
        }
        if (growB < NN) {
            half2 hh = __floats2half2_rn(d2, d3);
            *(half2*)&g_xh[(size_t)growB * 128 + c0] = hh;
        }
        float2 s2 = *(const float2*)(att_src + c0);
        float2 t2 = *(const float2*)(att_dst + c0);
        float psA_ = d0 * s2.x + d1 * s2.y;
        float pdA_ = d0 * t2.x + d1 * t2.y;
        float psB_ = d2 * s2.x + d3 * s2.y;
        float pdB_ = d2 * t2.x + d3 * t2.y;
        if (t < 8) { ps0A += psA_; pd0A += pdA_; ps0B += psB_; pd0B += pdB_; }
        else       { ps1A += psA_; pd1A += pdA_; ps1B += psB_; pd1B += pdB_; }
    }

    #pragma unroll
    for (int d = 1; d <= 2; d <<= 1) {
        ps0A += __shfl_xor_sync(0xffffffffu, ps0A, d);
        ps1A += __shfl_xor_sync(0xffffffffu, ps1A, d);
        pd0A += __shfl_xor_sync(0xffffffffu, pd0A, d);
        pd1A += __shfl_xor_sync(0xffffffffu, pd1A, d);
        ps0B += __shfl_xor_sync(0xffffffffu, ps0B, d);
        ps1B += __shfl_xor_sync(0xffffffffu, ps1B, d);
        pd0B += __shfl_xor_sync(0xffffffffu, pd0B, d);
        pd1B += __shfl_xor_sync(0xffffffffu, pd1B, d);
    }
    if (q == 0) {
        if (growA < NN) {
            *(float2*)&g_as[2 * growA] = make_float2(ps0A, ps1A);
            *(float2*)&g_ad[2 * growA] = make_float2(pd0A, pd1A);
        }
        if (growB < NN) {
            *(float2*)&g_as[2 * growB] = make_float2(ps0B, ps1B);
            *(float2*)&g_ad[2 * growB] = make_float2(pd0B, pd1B);
        }
    }
}

// ---------------- 2) single-pass decoupled-lookback scan -------------------
__global__ void k_scan() {
    __shared__ int warp_sums[8];
    __shared__ int warp_excl[8];
    __shared__ int s_prev;

    int b = blockIdx.x;
    int tid = threadIdx.x, lane = tid & 31, wid = tid >> 5;
    int base = b * 1024 + tid * 4;

    int4 c4 = *(int4*)&g_counts[base];
    int v0 = (base + 0 < NN) ? c4.x + 1 : 0;   // +1 self loop
    int v1 = (base + 1 < NN) ? c4.y + 1 : 0;
    int v2 = (base + 2 < NN) ? c4.z + 1 : 0;
    int v3 = (base + 3 < NN) ? c4.w + 1 : 0;
    int s = v0 + v1 + v2 + v3;

    int x = s;
    #pragma unroll
    for (int d = 1; d < 32; d <<= 1) {
        int t2 = __shfl_up_sync(0xffffffffu, x, d);
        if (lane >= d) x += t2;
    }
    if (lane == 31) warp_sums[wid] = x;
    __syncthreads();
    if (tid == 0) {
        int run = 0;
        #pragma unroll
        for (int i = 0; i < 8; i++) {
            int t2 = warp_sums[i];
            warp_excl[i] = run;
            run += t2;
        }
        atomicExch(&g_bsum[b], run);
    }
    __syncthreads();

    if (wid == 0) {
        int acc = 0;
        for (int p = lane; p < b; p += 32) {
            int v;
            do { v = ((volatile int*)g_bsum)[p]; } while (v == 0);
            acc += v;
        }
        #pragma unroll
        for (int d = 16; d >= 1; d >>= 1)
            acc += __shfl_xor_sync(0xffffffffu, acc, d);
        if (lane == 0) s_prev = acc;
    }
    __syncthreads();

    int excl = s_prev + warp_excl[wid] + (x - s);
    int4 ov = make_int4(excl, excl + v0, excl + v0 + v1, excl + v0 + v1 + v2);
    *(int4*)&g_offsets[base] = ov;
    *(int4*)&g_counts[base]  = make_int4(0, 0, 0, 0);

    __threadfence();
    __syncthreads();
    if (tid == 0) {
        int r = atomicAdd(&g_done, 1);
        if (r == NSCAN - 1) {
            for (int i = 0; i < NSCAN; i++) g_bsum[i] = 0;
            g_done = 0;
        }
    }
}

// ---------------- 3) scatter edges into CSR (atomic-free) ------------------
__global__ void k_scatter(const int* __restrict__ ei) {
    int t = blockIdx.x * blockDim.x + threadIdx.x;
    const int EQ = EE / 4;
    if (t < EQ) {
        int4 s = ((const int4*)ei)[t];
        int4 d = ((const int4*)(ei + EE))[t];
        int4 r = ((const int4*)g_rank)[t];
        g_ssrc[__ldg(&g_offsets[d.x]) + 1 + r.x] = s.x;
        g_ssrc[__ldg(&g_offsets[d.y]) + 1 + r.y] = s.y;
        g_ssrc[__ldg(&g_offsets[d.z]) + 1 + r.z] = s.z;
        g_ssrc[__ldg(&g_offsets[d.w]) + 1 + r.w] = s.w;
    } else if (t - EQ < NN) {
        int n = t - EQ;
        g_ssrc[__ldg(&g_offsets[n])] = n;   // self loop in slot 0 of segment
    }
}

// ---------------- 4) edge softmax + aggregate (smem-staged, pipelined) -----
__device__ __forceinline__ float leaky(float x) {
    return x > 0.f ? x : NEG_SLOPE * x;
}

__global__ void k_aggregate(const float* __restrict__ bias, float* __restrict__ out) {
    __shared__ float s_p[8][2][36];
    __shared__ int   s_off[8][32];

    int w = (blockIdx.x * blockDim.x + threadIdx.x) >> 5;
    if (w >= NN) return;
    int lane = threadIdx.x & 31;
    int h = lane >> 4;
    int ws = (threadIdx.x >> 5) & 7;
    int beg = g_offsets[w], end = g_offsets[w + 1];

    float ad0 = g_ad[2 * w + 0];
    float ad1 = g_ad[2 * w + 1];
    const char* xbase = (const char*)g_xh + lane * 8;

    float den0 = 0.f, den1 = 0.f;
    float4 acc = make_float4(0.f, 0.f, 0.f, 0.f);

    // prefetch chunk 0
    int idx = 0;
    float2 as2 = make_float2(0.f, 0.f);
    if (beg + lane < end) {
        idx = g_ssrc[beg + lane];
        as2 = *(const float2*)&g_as[2 * idx];
    }

    for (int base = beg; base < end; base += 32) {
        int nb = min(32, end - base);
        // phase 1: logits for this chunk (from prefetched regs)
        if (lane < nb) {
            float p0 = __expf(leaky(as2.x + ad0));
            float p1 = __expf(leaky(as2.y + ad1));
            den0 += p0;
            den1 += p1;
            s_p[ws][0][lane] = p0;
            s_p[ws][1][lane] = p1;
            s_off[ws][lane] = idx << 8;
        }
        // prefetch next chunk before the gather loop hides its latency
        int nbase = base + 32;
        if (nbase < end) {
            idx = 0;
            as2 = make_float2(0.f, 0.f);
            if (nbase + lane < end) {
                idx = g_ssrc[nbase + lane];
                as2 = *(const float2*)&g_as[2 * idx];
            }
        }
        __syncwarp();
        if (nb == 32) {
            #pragma unroll 8
            for (int jj = 0; jj < 32; jj++) {
                int off = s_off[ws][jj];
                float ph = s_p[ws][h][jj];
                uint2 hv = *(const uint2*)(xbase + off);
                float2 f01 = __half22float2(*(half2*)&hv.x);
                float2 f23 = __half22float2(*(half2*)&hv.y);
                acc.x += ph * f01.x;
                acc.y += ph * f01.y;
                acc.z += ph * f23.x;
                acc.w += ph * f23.y;
            }
        } else {
            for (int jj = 0; jj < nb; jj++) {
                int off = s_off[ws][jj];
                float ph = s_p[ws][h][jj];
                uint2 hv = *(const uint2*)(xbase + off);
                float2 f01 = __half22float2(*(half2*)&hv.x);
                float2 f23 = __half22float2(*(half2*)&hv.y);
                acc.x += ph * f01.x;
                acc.y += ph * f01.y;
                acc.z += ph * f23.x;
                acc.w += ph * f23.y;
            }
        }
        __syncwarp();
    }

    #pragma unroll
    for (int d = 16; d >= 1; d >>= 1) {
        den0 += __shfl_xor_sync(0xffffffffu, den0, d);
        den1 += __shfl_xor_sync(0xffffffffu, den1, d);
    }
    float inv = 1.0f / (h ? den1 : den0);

    float4 b = ((const float4*)bias)[lane];
    acc.x = acc.x * inv + b.x;
    acc.y = acc.y * inv + b.y;
    acc.z = acc.z * inv + b.z;
    acc.w = acc.w * inv + b.w;
    acc.x = acc.x > 0.f ? acc.x : expm1f(acc.x);
    acc.y = acc.y > 0.f ? acc.y : expm1f(acc.y);
    acc.z = acc.z > 0.f ? acc.z : expm1f(acc.z);
    acc.w = acc.w > 0.f ? acc.w : expm1f(acc.w);
    ((float4*)out)[(size_t)w * 32 + lane] = acc;
}

// ---------------- launch ----------------
extern "C" void kernel_launch(void* const* d_in, const int* in_sizes, int n_in,
                              void* d_out, int out_size) {
    const float* h_node  = (const float*)d_in[0];
    const int*   ei      = (const int*)d_in[1];
    const float* W       = (const float*)d_in[2];
    const float* att_src = (const float*)d_in[3];
    const float* att_dst = (const float*)d_in[4];
    const float* bias    = (const float*)d_in[5];
    float* out = (float*)d_out;

    k_wconv<<<16, 256>>>(W);
    int hist_blocks = (EE / 4 + 255) / 256;
    k_gemm_hist<<<G_GEMM + hist_blocks, 256>>>(h_node, att_src, att_dst, ei);
    k_scan<<<NSCAN, 256>>>();
    k_scatter<<<(EE / 4 + NN + 255) / 256, 256>>>(ei);
    k_aggregate<<<(NN * 32 + 255) / 256, 256>>>(bias, out);
}